// round 13
// baseline (speedup 1.0000x reference)
#include <cuda_runtime.h>
#include <cuda_bf16.h>
#include <math.h>
#include <stdint.h>

#define NTOK 16384
#define DM   1024
#define NE   4
#define DH   2048

// ------------------------- device scratch ------------------------------------
__device__ int   g_count[NE];
__device__ int   g_tok [NE * NTOK];
__device__ int   g_eid [NTOK * 2];
__device__ int   g_slot[NTOK * 2];
__device__ float g_wt  [NTOK * 2];
__device__ float g_H[(size_t)NE * NTOK * DH];
__device__ float g_Z[(size_t)NE * NTOK * DM];

// ------------------------- PTX helpers (sm_80-class only) ---------------------
__device__ __forceinline__ uint32_t smem_u32(const void* p) {
    uint32_t a;
    asm("{ .reg .u64 t; cvta.to.shared.u64 t, %1; cvt.u32.u64 %0, t; }" : "=r"(a) : "l"(p));
    return a;
}
__device__ __forceinline__ void cpa16(uint32_t dst, const void* src) {
    asm volatile("cp.async.cg.shared.global [%0], [%1], 16;" :: "r"(dst), "l"(src));
}
__device__ __forceinline__ void cpa_commit() {
    asm volatile("cp.async.commit_group;" ::: "memory");
}
template <int N> __device__ __forceinline__ void cpa_wait() {
    asm volatile("cp.async.wait_group %0;" :: "n"(N) : "memory");
}
__device__ __forceinline__ void ldsm4(uint32_t* r, uint32_t addr) {
    asm volatile("ldmatrix.sync.aligned.m8n8.x4.shared.b16 {%0,%1,%2,%3}, [%4];"
                 : "=r"(r[0]), "=r"(r[1]), "=r"(r[2]), "=r"(r[3]) : "r"(addr));
}
__device__ __forceinline__ uint32_t f2tf32(uint32_t bits) {
    uint32_t o;
    float f = __uint_as_float(bits);
    asm("cvt.rna.tf32.f32 %0, %1;" : "=r"(o) : "f"(f));
    return o;
}
__device__ __forceinline__ void mma_tf32(float* c, const uint32_t* a,
                                         uint32_t b0, uint32_t b1) {
    asm volatile(
        "mma.sync.aligned.m16n8k8.row.col.f32.tf32.tf32.f32 "
        "{%0,%1,%2,%3}, {%4,%5,%6,%7}, {%8,%9}, {%0,%1,%2,%3};"
        : "+f"(c[0]), "+f"(c[1]), "+f"(c[2]), "+f"(c[3])
        : "r"(a[0]), "r"(a[1]), "r"(a[2]), "r"(a[3]), "r"(b0), "r"(b1));
}

// ------------------------- small kernels -------------------------------------
__global__ void reset_kernel() {
    if (threadIdx.x < NE) g_count[threadIdx.x] = 0;
}

__global__ void gate_kernel(const float* __restrict__ x,
                            const float* __restrict__ gw) {
    int t = blockIdx.x, tid = threadIdx.x, w = tid >> 5, lane = tid & 31;
    const float4* xr = (const float4*)(x + (size_t)t * DM);
    const float4* gr = (const float4*)(gw + (size_t)w * DM);
    float s = 0.f;
    for (int k = lane; k < DM / 4; k += 32) {
        float4 a = xr[k], b = gr[k];
        s += a.x * b.x + a.y * b.y + a.z * b.z + a.w * b.w;
    }
    #pragma unroll
    for (int o = 16; o; o >>= 1) s += __shfl_xor_sync(0xffffffffu, s, o);
    __shared__ float sc[NE];
    if (lane == 0) sc[w] = s;
    __syncthreads();
    if (tid == 0) {
        int i0 = 0;
        #pragma unroll
        for (int i = 1; i < NE; i++) if (sc[i] > sc[i0]) i0 = i;
        int i1 = -1;
        #pragma unroll
        for (int i = 0; i < NE; i++) {
            if (i == i0) continue;
            if (i1 < 0 || sc[i] > sc[i1]) i1 = i;
        }
        float m = fmaxf(sc[i0], sc[i1]);
        float e0 = expf(sc[i0] - m), e1 = expf(sc[i1] - m);
        float inv = 1.f / (e0 + e1);
        int s0 = atomicAdd(&g_count[i0], 1);
        int s1 = atomicAdd(&g_count[i1], 1);
        g_eid [t * 2] = i0;  g_eid [t * 2 + 1] = i1;
        g_slot[t * 2] = s0;  g_slot[t * 2 + 1] = s1;
        g_wt  [t * 2] = e0 * inv;
        g_wt  [t * 2 + 1] = e1 * inv;
        g_tok[i0 * NTOK + s0] = t;
        g_tok[i1 * NTOK + s1] = t;
    }
}

// ------------------------- tf32 HMMA GEMM ------------------------------------
// C[m,n] = sum_k A[m,k]*B[n,k], single-pass tf32 (cvt.rna in-register).
// CTA 128x256, BK=32 fp32 (128B rows), 16 warps (2m x 8n), warp tile 64x32.
// 4-stage cp.async ring; XOR chunk swizzle — identical layout to R12.
#define BM 128
#define BN 256
#define BK 32
#define STG 49152
#define SMEM_TOTAL (4 * STG)   // 196608

template <int PHASE>
__global__ void __launch_bounds__(512, 1)
gemm_tf32(const float* __restrict__ x_in,
          const float* __restrict__ W,
          const float* __restrict__ bias) {
    constexpr int K = (PHASE == 1) ? DM : DH;
    constexpr int N = (PHASE == 1) ? DH : DM;
    constexpr int S = K / BK;

    const int e   = blockIdx.z;
    const int cnt = g_count[e];
    const int m0  = blockIdx.y * BM;
    if (m0 >= cnt) return;
    const int n0  = blockIdx.x * BN;

    extern __shared__ char dsm[];
    const uint32_t BUF = smem_u32(dsm);

    const int tid  = threadIdx.x;
    const int lane = tid & 31;
    const int wid  = tid >> 5;        // 0..15
    const int wm   = wid >> 3;        // 0..1  (m base wm*64)
    const int wn   = wid & 7;         // 0..7  (n base wn*32)

    // -------- cp.async mapping: 8 threads per 128B row, 6 chunks/thread -------
    const int grpi = tid >> 3;        // 0..63
    const int chnk = tid & 7;
    const uint32_t pchunk = (uint32_t)((chnk ^ (grpi & 7)) << 4);
    const int csrc = chnk * 4;

    // A rows: grpi + 64p, p=0..1
    const float* arow[2];
    #pragma unroll
    for (int p = 0; p < 2; p++) {
        int r = grpi + 64 * p;
        if (PHASE == 1) {
            int row = m0 + r;
            int tok = (row < cnt) ? g_tok[e * NTOK + row] : 0;
            arow[p] = x_in + (size_t)tok * DM;
        } else {
            arow[p] = g_H + ((size_t)e * NTOK + m0 + r) * DH;
        }
    }
    // B rows: grpi + 64p, p=0..3
    const float* brow[4];
    #pragma unroll
    for (int p = 0; p < 4; p++)
        brow[p] = W + ((size_t)e * N + n0 + grpi + 64 * p) * K;

    auto load_stage = [&](int s) {
        const int kb = s * BK;
        const uint32_t sb = BUF + (uint32_t)(s & 3) * STG;
        #pragma unroll
        for (int p = 0; p < 2; p++)
            cpa16(sb + (uint32_t)((grpi + 64 * p) * 128) + pchunk, arow[p] + kb + csrc);
        #pragma unroll
        for (int p = 0; p < 4; p++)
            cpa16(sb + 16384u + (uint32_t)((grpi + 64 * p) * 128) + pchunk, brow[p] + kb + csrc);
        cpa_commit();
    };

    // -------- ldsm per-lane constants (same as R12) --------
    const uint32_t arl  = (uint32_t)((lane & 7) + ((lane >> 3) & 1) * 8);
    const uint32_t asel = (uint32_t)(lane >> 4);
    const uint32_t brl  = (uint32_t)((lane & 7) + (lane >> 4) * 8);
    const uint32_t bsel = (uint32_t)((lane >> 3) & 1);
    const uint32_t lx   = (uint32_t)(lane & 7);

    float acc[4][4][4];
    #pragma unroll
    for (int i = 0; i < 4; i++)
        #pragma unroll
        for (int j = 0; j < 4; j++)
            #pragma unroll
            for (int q = 0; q < 4; q++) acc[i][j][q] = 0.f;

    load_stage(0);
    load_stage(1);
    load_stage(2);

    for (int s = 0; s < S; s++) {
        cpa_wait<2>();
        __syncthreads();
        if (s + 3 < S) load_stage(s + 3);
        else cpa_commit();              // keep group count uniform

        const uint32_t sb = BUF + (uint32_t)(s & 3) * STG;
        const uint32_t aB = sb + (uint32_t)(wm * 64) * 128 + arl * 128;
        const uint32_t bB = sb + 16384u + (uint32_t)(wn * 32) * 128 + brl * 128;

        #pragma unroll
        for (uint32_t kk = 0; kk < 4; kk++) {
            const uint32_t ac = ((2 * kk + asel) ^ lx) << 4;
            const uint32_t bc = ((2 * kk + bsel) ^ lx) << 4;
            uint32_t a[4][4], b[2][4];
            #pragma unroll
            for (int mt = 0; mt < 4; mt++) {
                ldsm4(a[mt], aB + (uint32_t)(mt * 16 * 128) + ac);
                #pragma unroll
                for (int q = 0; q < 4; q++) a[mt][q] = f2tf32(a[mt][q]);
            }
            #pragma unroll
            for (int nb = 0; nb < 2; nb++) {
                ldsm4(b[nb], bB + (uint32_t)(nb * 16 * 128) + bc);
                #pragma unroll
                for (int q = 0; q < 4; q++) b[nb][q] = f2tf32(b[nb][q]);
            }
            #pragma unroll
            for (int mt = 0; mt < 4; mt++)
                #pragma unroll
                for (int nb = 0; nb < 2; nb++) {
                    mma_tf32(acc[mt][2 * nb],     a[mt], b[nb][0], b[nb][1]);
                    mma_tf32(acc[mt][2 * nb + 1], a[mt], b[nb][2], b[nb][3]);
                }
        }
    }

    // -------- epilogue --------
    const int grp = lane >> 2, qid = lane & 3;
    float bc2[4][2];
    #pragma unroll
    for (int nt = 0; nt < 4; nt++) {
        int col = n0 + wn * 32 + nt * 8 + qid * 2;
        bc2[nt][0] = __ldg(bias + e * N + col);
        bc2[nt][1] = __ldg(bias + e * N + col + 1);
    }
    #pragma unroll
    for (int mt = 0; mt < 4; mt++) {
        #pragma unroll
        for (int h = 0; h < 2; h++) {
            int r = m0 + wm * 64 + mt * 16 + grp + h * 8;
            if (r >= cnt) continue;
            #pragma unroll
            for (int nt = 0; nt < 4; nt++) {
                int col = n0 + wn * 32 + nt * 8 + qid * 2;
                float v0 = acc[mt][nt][h * 2 + 0] + bc2[nt][0];
                float v1 = acc[mt][nt][h * 2 + 1] + bc2[nt][1];
                if (PHASE == 1) {
                    v0 = 0.5f * v0 * (1.f + erff(v0 * 0.70710678118654752f));
                    v1 = 0.5f * v1 * (1.f + erff(v1 * 0.70710678118654752f));
                    float2 o = {v0, v1};
                    *(float2*)(g_H + ((size_t)e * NTOK + r) * DH + col) = o;
                } else {
                    float2 o = {v0, v1};
                    *(float2*)(g_Z + ((size_t)e * NTOK + r) * DM + col) = o;
                }
            }
        }
    }
}

// ------------------------- combine -------------------------------------------
__global__ void combine_kernel(const float* __restrict__ x,
                               const float* __restrict__ gamma,
                               const float* __restrict__ beta,
                               float* __restrict__ out) {
    const int t = blockIdx.x, tid = threadIdx.x;
    __shared__ float ssum[8], ssq[8];
    const float4 xv = *(const float4*)(x + (size_t)t * DM + tid * 4);
    float acc[4] = {0.f, 0.f, 0.f, 0.f};
    #pragma unroll
    for (int p = 0; p < 2; p++) {
        int e = g_eid[t * 2 + p], s = g_slot[t * 2 + p];
        float wgt = g_wt[t * 2 + p];
        const float4 zv = *(const float4*)(g_Z + ((size_t)e * NTOK + s) * DM + tid * 4);
        float z[4] = {xv.x + zv.x, xv.y + zv.y, xv.z + zv.z, xv.w + zv.w};
        float sum = 0.f, sq = 0.f;
        #pragma unroll
        for (int i = 0; i < 4; i++) { sum += z[i]; sq += z[i] * z[i]; }
        #pragma unroll
        for (int o = 16; o; o >>= 1) {
            sum += __shfl_xor_sync(0xffffffffu, sum, o);
            sq  += __shfl_xor_sync(0xffffffffu, sq,  o);
        }
        int w = tid >> 5, lane = tid & 31;
        if (lane == 0) { ssum[w] = sum; ssq[w] = sq; }
        __syncthreads();
        float tsum = 0.f, tsq = 0.f;
        #pragma unroll
        for (int i = 0; i < 8; i++) { tsum += ssum[i]; tsq += ssq[i]; }
        __syncthreads();
        float mu = tsum * (1.f / DM);
        float var = tsq * (1.f / DM) - mu * mu;
        float rstd = rsqrtf(var + 1e-6f);
        const float4 gv = *(const float4*)(gamma + (size_t)e * DM + tid * 4);
        const float4 bv = *(const float4*)(beta  + (size_t)e * DM + tid * 4);
        const float g4[4] = {gv.x, gv.y, gv.z, gv.w};
        const float b4[4] = {bv.x, bv.y, bv.z, bv.w};
        #pragma unroll
        for (int i = 0; i < 4; i++)
            acc[i] += wgt * ((z[i] - mu) * rstd * g4[i] + b4[i]);
    }
    float4 o4 = {acc[0], acc[1], acc[2], acc[3]};
    *(float4*)(out + (size_t)t * DM + tid * 4) = o4;
}

// ------------------------- launch --------------------------------------------
extern "C" void kernel_launch(void* const* d_in, const int* in_sizes, int n_in,
                              void* d_out, int out_size) {
    const float* x     = (const float*)d_in[0];
    const float* gw    = (const float*)d_in[1];
    const float* w1    = (const float*)d_in[2];
    const float* b1    = (const float*)d_in[3];
    const float* w2    = (const float*)d_in[4];
    const float* b2    = (const float*)d_in[5];
    const float* gamma = (const float*)d_in[6];
    const float* beta  = (const float*)d_in[7];
    float* out = (float*)d_out;

    cudaFuncSetAttribute(gemm_tf32<1>, cudaFuncAttributeMaxDynamicSharedMemorySize, SMEM_TOTAL);
    cudaFuncSetAttribute(gemm_tf32<2>, cudaFuncAttributeMaxDynamicSharedMemorySize, SMEM_TOTAL);

    reset_kernel<<<1, 32>>>();
    gate_kernel<<<NTOK, 128>>>(x, gw);

    dim3 g1(DH / BN, NTOK / BM, NE);
    gemm_tf32<1><<<g1, 512, SMEM_TOTAL>>>(x, w1, b1);

    dim3 g2(DM / BN, NTOK / BM, NE);
    gemm_tf32<2><<<g2, 512, SMEM_TOTAL>>>(nullptr, w2, b2);

    combine_kernel<<<NTOK, 256>>>(x, gamma, beta, out);
}

// round 15
// speedup vs baseline: 1.7222x; 1.7222x over previous
#include <cuda_runtime.h>
#include <cuda_bf16.h>
#include <math.h>
#include <stdint.h>

#define NTOK 16384
#define DM   1024
#define NE   4
#define DH   2048

// ------------------------- device scratch ------------------------------------
__device__ int   g_count[NE];
__device__ int   g_tok [NE * NTOK];
__device__ int   g_eid [NTOK * 2];
__device__ int   g_slot[NTOK * 2];
__device__ float g_wt  [NTOK * 2];
__device__ float g_xr [(size_t)NTOK * DM];        // tf32-rounded x
__device__ float g_w1r[(size_t)NE * DH * DM];     // tf32-rounded w1
__device__ float g_w2r[(size_t)NE * DM * DH];     // tf32-rounded w2
__device__ float g_H[(size_t)NE * NTOK * DH];     // tf32-rounded gelu(xW1^T+b1)
__device__ float g_Z[(size_t)NE * NTOK * DM];

// ------------------------- PTX helpers (sm_80-class only) ---------------------
__device__ __forceinline__ uint32_t smem_u32(const void* p) {
    uint32_t a;
    asm("{ .reg .u64 t; cvta.to.shared.u64 t, %1; cvt.u32.u64 %0, t; }" : "=r"(a) : "l"(p));
    return a;
}
__device__ __forceinline__ void cpa16(uint32_t dst, const void* src) {
    asm volatile("cp.async.cg.shared.global [%0], [%1], 16;" :: "r"(dst), "l"(src));
}
__device__ __forceinline__ void cpa_commit() {
    asm volatile("cp.async.commit_group;" ::: "memory");
}
template <int N> __device__ __forceinline__ void cpa_wait() {
    asm volatile("cp.async.wait_group %0;" :: "n"(N) : "memory");
}
__device__ __forceinline__ void ldsm4(uint32_t* r, uint32_t addr) {
    asm volatile("ldmatrix.sync.aligned.m8n8.x4.shared.b16 {%0,%1,%2,%3}, [%4];"
                 : "=r"(r[0]), "=r"(r[1]), "=r"(r[2]), "=r"(r[3]) : "r"(addr));
}
__device__ __forceinline__ float f2tf32f(float f) {
    uint32_t o;
    asm("cvt.rna.tf32.f32 %0, %1;" : "=r"(o) : "f"(f));
    return __uint_as_float(o);
}
__device__ __forceinline__ void mma_tf32(float* c, const uint32_t* a,
                                         uint32_t b0, uint32_t b1) {
    asm volatile(
        "mma.sync.aligned.m16n8k8.row.col.f32.tf32.tf32.f32 "
        "{%0,%1,%2,%3}, {%4,%5,%6,%7}, {%8,%9}, {%0,%1,%2,%3};"
        : "+f"(c[0]), "+f"(c[1]), "+f"(c[2]), "+f"(c[3])
        : "r"(a[0]), "r"(a[1]), "r"(a[2]), "r"(a[3]), "r"(b0), "r"(b1));
}

// ------------------------- small kernels -------------------------------------
__global__ void reset_kernel() {
    if (threadIdx.x < NE) g_count[threadIdx.x] = 0;
}

__global__ void gate_kernel(const float* __restrict__ x,
                            const float* __restrict__ gw) {
    int t = blockIdx.x, tid = threadIdx.x, w = tid >> 5, lane = tid & 31;
    const float4* xr = (const float4*)(x + (size_t)t * DM);
    const float4* gr = (const float4*)(gw + (size_t)w * DM);
    float s = 0.f;
    for (int k = lane; k < DM / 4; k += 32) {
        float4 a = xr[k], b = gr[k];
        s += a.x * b.x + a.y * b.y + a.z * b.z + a.w * b.w;
    }
    #pragma unroll
    for (int o = 16; o; o >>= 1) s += __shfl_xor_sync(0xffffffffu, s, o);
    __shared__ float sc[NE];
    if (lane == 0) sc[w] = s;
    __syncthreads();
    if (tid == 0) {
        int i0 = 0;
        #pragma unroll
        for (int i = 1; i < NE; i++) if (sc[i] > sc[i0]) i0 = i;
        int i1 = -1;
        #pragma unroll
        for (int i = 0; i < NE; i++) {
            if (i == i0) continue;
            if (i1 < 0 || sc[i] > sc[i1]) i1 = i;
        }
        float m = fmaxf(sc[i0], sc[i1]);
        float e0 = expf(sc[i0] - m), e1 = expf(sc[i1] - m);
        float inv = 1.f / (e0 + e1);
        int s0 = atomicAdd(&g_count[i0], 1);
        int s1 = atomicAdd(&g_count[i1], 1);
        g_eid [t * 2] = i0;  g_eid [t * 2 + 1] = i1;
        g_slot[t * 2] = s0;  g_slot[t * 2 + 1] = s1;
        g_wt  [t * 2] = e0 * inv;
        g_wt  [t * 2 + 1] = e1 * inv;
        g_tok[i0 * NTOK + s0] = t;
        g_tok[i1 * NTOK + s1] = t;
    }
}

// fp32 -> tf32-rounded fp32, 8 elems/thread
__global__ void round_kernel(const float* __restrict__ src,
                             float* __restrict__ dst, int n8) {
    int i = blockIdx.x * blockDim.x + threadIdx.x;
    if (i >= n8) return;
    float4 v0 = ((const float4*)src)[i * 2];
    float4 v1 = ((const float4*)src)[i * 2 + 1];
    v0.x = f2tf32f(v0.x); v0.y = f2tf32f(v0.y);
    v0.z = f2tf32f(v0.z); v0.w = f2tf32f(v0.w);
    v1.x = f2tf32f(v1.x); v1.y = f2tf32f(v1.y);
    v1.z = f2tf32f(v1.z); v1.w = f2tf32f(v1.w);
    ((float4*)dst)[i * 2]     = v0;
    ((float4*)dst)[i * 2 + 1] = v1;
}

// ------------------------- tf32 HMMA GEMM ------------------------------------
// C[m,n] = sum_k A[m,k]*B[n,k]; inputs pre-rounded to tf32 in GMEM (no in-loop cvt).
// CTA 128x256, BK=32 fp32 (128B rows), 8 warps (2m x 4n), warp tile 64x64.
// 4-stage cp.async ring; XOR chunk swizzle; fragment double-buffer per kk.
#define BM 128
#define BN 256
#define BK 32
#define STG 49152
#define SMEM_TOTAL (4 * STG)   // 196608

template <int PHASE>
__global__ void __launch_bounds__(256, 1)
gemm_tf32(const float* __restrict__ bias) {
    constexpr int K = (PHASE == 1) ? DM : DH;
    constexpr int N = (PHASE == 1) ? DH : DM;
    constexpr int S = K / BK;

    const int e   = blockIdx.z;
    const int cnt = g_count[e];
    const int m0  = blockIdx.y * BM;
    if (m0 >= cnt) return;
    const int n0  = blockIdx.x * BN;

    extern __shared__ char dsm[];
    const uint32_t BUF = smem_u32(dsm);

    const int tid  = threadIdx.x;
    const int lane = tid & 31;
    const int wid  = tid >> 5;        // 0..7
    const int wm   = wid >> 2;        // 0..1
    const int wn   = wid & 3;         // 0..3

    // -------- cp.async mapping --------
    const int grpi = tid >> 3;        // 0..31
    const int chnk = tid & 7;
    const uint32_t pchunk = (uint32_t)((chnk ^ (grpi & 7)) << 4);
    const int csrc = chnk * 4;

    const float* arow[4];
    #pragma unroll
    for (int p = 0; p < 4; p++) {
        int r = grpi + 32 * p;
        if (PHASE == 1) {
            int row = m0 + r;
            int tok = (row < cnt) ? g_tok[e * NTOK + row] : 0;
            arow[p] = g_xr + (size_t)tok * DM;
        } else {
            arow[p] = g_H + ((size_t)e * NTOK + m0 + r) * DH;
        }
    }
    const float* W = (PHASE == 1) ? g_w1r : g_w2r;
    const float* brow[8];
    #pragma unroll
    for (int p = 0; p < 8; p++)
        brow[p] = W + ((size_t)e * N + n0 + grpi + 32 * p) * K;

    auto load_stage = [&](int s) {
        const int kb = s * BK;
        const uint32_t sb = BUF + (uint32_t)(s & 3) * STG;
        #pragma unroll
        for (int p = 0; p < 4; p++)
            cpa16(sb + (uint32_t)((grpi + 32 * p) * 128) + pchunk, arow[p] + kb + csrc);
        #pragma unroll
        for (int p = 0; p < 8; p++)
            cpa16(sb + 16384u + (uint32_t)((grpi + 32 * p) * 128) + pchunk, brow[p] + kb + csrc);
        cpa_commit();
    };

    // -------- ldsm per-lane constants --------
    const uint32_t arl  = (uint32_t)((lane & 7) + ((lane >> 3) & 1) * 8);
    const uint32_t asel = (uint32_t)(lane >> 4);
    const uint32_t brl  = (uint32_t)((lane & 7) + (lane >> 4) * 8);
    const uint32_t bsel = (uint32_t)((lane >> 3) & 1);
    const uint32_t lx   = (uint32_t)(lane & 7);

    float acc[4][8][4];
    #pragma unroll
    for (int i = 0; i < 4; i++)
        #pragma unroll
        for (int j = 0; j < 8; j++)
            #pragma unroll
            for (int q = 0; q < 4; q++) acc[i][j][q] = 0.f;

    uint32_t af[2][4][4], bf[2][4][4];

    load_stage(0);
    load_stage(1);
    load_stage(2);

    for (int s = 0; s < S; s++) {
        cpa_wait<2>();
        __syncthreads();
        if (s + 3 < S) load_stage(s + 3);
        else cpa_commit();              // keep group count uniform

        const uint32_t sb = BUF + (uint32_t)(s & 3) * STG;
        const uint32_t aB = sb + (uint32_t)(wm * 64) * 128 + arl * 128;
        const uint32_t bB = sb + 16384u + (uint32_t)(wn * 64) * 128 + brl * 128;

        // fragment prologue: kk = 0 into buffer 0
        {
            const uint32_t ac = (asel ^ lx) << 4;
            const uint32_t bc = (bsel ^ lx) << 4;
            #pragma unroll
            for (int mt = 0; mt < 4; mt++)
                ldsm4(af[0][mt], aB + (uint32_t)(mt * 16 * 128) + ac);
            #pragma unroll
            for (int nb = 0; nb < 4; nb++)
                ldsm4(bf[0][nb], bB + (uint32_t)(nb * 16 * 128) + bc);
        }

        #pragma unroll
        for (uint32_t kk = 0; kk < 4; kk++) {
            const int cur = kk & 1;
            if (kk < 3) {
                const int nxt = cur ^ 1;
                const uint32_t ac = ((2 * (kk + 1) + asel) ^ lx) << 4;
                const uint32_t bc = ((2 * (kk + 1) + bsel) ^ lx) << 4;
                #pragma unroll
                for (int mt = 0; mt < 4; mt++)
                    ldsm4(af[nxt][mt], aB + (uint32_t)(mt * 16 * 128) + ac);
                #pragma unroll
                for (int nb = 0; nb < 4; nb++)
                    ldsm4(bf[nxt][nb], bB + (uint32_t)(nb * 16 * 128) + bc);
            }
            #pragma unroll
            for (int mt = 0; mt < 4; mt++)
                #pragma unroll
                for (int nb = 0; nb < 4; nb++) {
                    mma_tf32(acc[mt][2 * nb],     af[cur][mt], bf[cur][nb][0], bf[cur][nb][1]);
                    mma_tf32(acc[mt][2 * nb + 1], af[cur][mt], bf[cur][nb][2], bf[cur][nb][3]);
                }
        }
    }

    // -------- epilogue --------
    const int grp = lane >> 2, qid = lane & 3;
    float bc2[8][2];
    #pragma unroll
    for (int nt = 0; nt < 8; nt++) {
        int col = n0 + wn * 64 + nt * 8 + qid * 2;
        bc2[nt][0] = __ldg(bias + e * N + col);
        bc2[nt][1] = __ldg(bias + e * N + col + 1);
    }
    #pragma unroll
    for (int mt = 0; mt < 4; mt++) {
        #pragma unroll
        for (int h = 0; h < 2; h++) {
            int r = m0 + wm * 64 + mt * 16 + grp + h * 8;
            if (r >= cnt) continue;
            #pragma unroll
            for (int nt = 0; nt < 8; nt++) {
                int col = n0 + wn * 64 + nt * 8 + qid * 2;
                float v0 = acc[mt][nt][h * 2 + 0] + bc2[nt][0];
                float v1 = acc[mt][nt][h * 2 + 1] + bc2[nt][1];
                if (PHASE == 1) {
                    v0 = 0.5f * v0 * (1.f + erff(v0 * 0.70710678118654752f));
                    v1 = 0.5f * v1 * (1.f + erff(v1 * 0.70710678118654752f));
                    // pre-round for GEMM2's tf32 consumption
                    float2 o = {f2tf32f(v0), f2tf32f(v1)};
                    *(float2*)(g_H + ((size_t)e * NTOK + r) * DH + col) = o;
                } else {
                    float2 o = {v0, v1};
                    *(float2*)(g_Z + ((size_t)e * NTOK + r) * DM + col) = o;
                }
            }
        }
    }
}

// ------------------------- combine -------------------------------------------
__global__ void combine_kernel(const float* __restrict__ x,
                               const float* __restrict__ gamma,
                               const float* __restrict__ beta,
                               float* __restrict__ out) {
    const int t = blockIdx.x, tid = threadIdx.x;
    __shared__ float ssum[8], ssq[8];
    const float4 xv = *(const float4*)(x + (size_t)t * DM + tid * 4);
    float acc[4] = {0.f, 0.f, 0.f, 0.f};
    #pragma unroll
    for (int p = 0; p < 2; p++) {
        int e = g_eid[t * 2 + p], s = g_slot[t * 2 + p];
        float wgt = g_wt[t * 2 + p];
        const float4 zv = *(const float4*)(g_Z + ((size_t)e * NTOK + s) * DM + tid * 4);
        float z[4] = {xv.x + zv.x, xv.y + zv.y, xv.z + zv.z, xv.w + zv.w};
        float sum = 0.f, sq = 0.f;
        #pragma unroll
        for (int i = 0; i < 4; i++) { sum += z[i]; sq += z[i] * z[i]; }
        #pragma unroll
        for (int o = 16; o; o >>= 1) {
            sum += __shfl_xor_sync(0xffffffffu, sum, o);
            sq  += __shfl_xor_sync(0xffffffffu, sq,  o);
        }
        int w = tid >> 5, lane = tid & 31;
        if (lane == 0) { ssum[w] = sum; ssq[w] = sq; }
        __syncthreads();
        float tsum = 0.f, tsq = 0.f;
        #pragma unroll
        for (int i = 0; i < 8; i++) { tsum += ssum[i]; tsq += ssq[i]; }
        __syncthreads();
        float mu = tsum * (1.f / DM);
        float var = tsq * (1.f / DM) - mu * mu;
        float rstd = rsqrtf(var + 1e-6f);
        const float4 gv = *(const float4*)(gamma + (size_t)e * DM + tid * 4);
        const float4 bv = *(const float4*)(beta  + (size_t)e * DM + tid * 4);
        const float g4[4] = {gv.x, gv.y, gv.z, gv.w};
        const float b4[4] = {bv.x, bv.y, bv.z, bv.w};
        #pragma unroll
        for (int i = 0; i < 4; i++)
            acc[i] += wgt * ((z[i] - mu) * rstd * g4[i] + b4[i]);
    }
    float4 o4 = {acc[0], acc[1], acc[2], acc[3]};
    *(float4*)(out + (size_t)t * DM + tid * 4) = o4;
}

// ------------------------- launch --------------------------------------------
extern "C" void kernel_launch(void* const* d_in, const int* in_sizes, int n_in,
                              void* d_out, int out_size) {
    const float* x     = (const float*)d_in[0];
    const float* gw    = (const float*)d_in[1];
    const float* w1    = (const float*)d_in[2];
    const float* b1    = (const float*)d_in[3];
    const float* w2    = (const float*)d_in[4];
    const float* b2    = (const float*)d_in[5];
    const float* gamma = (const float*)d_in[6];
    const float* beta  = (const float*)d_in[7];
    float* out = (float*)d_out;

    cudaFuncSetAttribute(gemm_tf32<1>, cudaFuncAttributeMaxDynamicSharedMemorySize, SMEM_TOTAL);
    cudaFuncSetAttribute(gemm_tf32<2>, cudaFuncAttributeMaxDynamicSharedMemorySize, SMEM_TOTAL);

    void *pxr, *pw1r, *pw2r;
    cudaGetSymbolAddress(&pxr,  g_xr);
    cudaGetSymbolAddress(&pw1r, g_w1r);
    cudaGetSymbolAddress(&pw2r, g_w2r);

    reset_kernel<<<1, 32>>>();
    gate_kernel<<<NTOK, 128>>>(x, gw);

    {
        int n8 = NTOK * DM / 8;
        round_kernel<<<(n8 + 255) / 256, 256>>>(x, (float*)pxr, n8);
    }
    {
        int n8 = NE * DH * DM / 8;
        round_kernel<<<(n8 + 255) / 256, 256>>>(w1, (float*)pw1r, n8);
        round_kernel<<<(n8 + 255) / 256, 256>>>(w2, (float*)pw2r, n8);
    }

    dim3 g1(DH / BN, NTOK / BM, NE);
    gemm_tf32<1><<<g1, 256, SMEM_TOTAL>>>(b1);

    dim3 g2(DM / BN, NTOK / BM, NE);
    gemm_tf32<2><<<g2, 256, SMEM_TOTAL>>>(b2);

    combine_kernel<<<NTOK, 256>>>(x, gamma, beta, out);
}